// round 11
// baseline (speedup 1.0000x reference)
#include <cuda_runtime.h>
#include <cstdint>

// Depthwise causal FIR conv1d, K=31, fp32.
// x: (8, 4096, 2048) channel-last.  w: (2048, 31).  y like x.
//
// Round-11: R5/R8 register-window design tuned for 16 warps/SM.
//  - thread = channel pair (float2), TT=128 outputs, CHUNK=4, full unroll
//  - 34-slot circular register window (static mod-34), direct LDG.64 prefetch
//  - taps in smem as float4 tap-PAIRS (15 x LDS.128 + 1 x LDS.64 per chunk),
//    pinned with asm volatile + 3-slot rotation -> ptxas cannot hoist
//  - true reg demand ~112 -> __launch_bounds__(64,8) 128-reg cap is safe:
//    8 blocks = 16 warps/SM (R9 spilled because CHUNK=8 demand was ~130+)
//  - streaming stores (st.global.cs): y is write-once, keep L2 for x halo

#define BB 8
#define LL 4096
#define CPAIR 1024
#define KK 31
#define CHUNK 4
#define TT 128
#define NCHUNK 32
#define WBUF 34          // 30 halo + 4 current
#define NPAIR 15         // tap pairs 0..14 -> taps 0..29; tap 30 separate
#define THREADS 64

__device__ __forceinline__ float2 ffma2(float2 a, float2 b, float2 c) {
    float2 d;
    asm("fma.rn.f32x2 %0, %1, %2, %3;"
        : "=l"(*reinterpret_cast<unsigned long long*>(&d))
        : "l"(*reinterpret_cast<const unsigned long long*>(&a)),
          "l"(*reinterpret_cast<const unsigned long long*>(&b)),
          "l"(*reinterpret_cast<const unsigned long long*>(&c)));
    return d;
}

// Pinned LDS (volatile: ptxas cannot hoist/batch these).
__device__ __forceinline__ float4 lds_w4(uint32_t addr) {
    float4 v;
    asm volatile("ld.shared.v4.f32 {%0, %1, %2, %3}, [%4];"
                 : "=f"(v.x), "=f"(v.y), "=f"(v.z), "=f"(v.w) : "r"(addr));
    return v;
}
__device__ __forceinline__ float2 lds_w2(uint32_t addr) {
    float2 v;
    asm volatile("ld.shared.v2.f32 {%0, %1}, [%2];"
                 : "=f"(v.x), "=f"(v.y) : "r"(addr));
    return v;
}

__device__ __forceinline__ void stg_cs(float2* p, float2 v) {
    asm volatile("st.global.cs.v2.f32 [%0], {%1, %2};"
                 :: "l"(p), "f"(v.x), "f"(v.y) : "memory");
}

__global__ __launch_bounds__(THREADS, 8)
void _DepthwiseFIRConv1d_kernel(const float* __restrict__ x,
                                const float* __restrict__ w,
                                float* __restrict__ y) {
    // ws4[p][tid] = (w0[2p], w1[2p], w0[2p+1], w1[2p+1]); ws30 = tap 30.
    __shared__ float4 ws4[NPAIR][THREADS];               // 15360 B
    __shared__ float2 ws30[THREADS];                     //   512 B

    const int tid = threadIdx.x;
    const int cpi = blockIdx.x * THREADS + tid;          // channel pair 0..1023
    const int l0  = blockIdx.y * TT;
    const int b   = blockIdx.z;

    const float2* xb = reinterpret_cast<const float2*>(x) + (size_t)b * LL * CPAIR + cpi;
    float2*       yb = reinterpret_cast<float2*>(y) + ((size_t)b * LL + l0) * CPAIR + cpi;
    const int base = l0 - (KK - 1);

    // Stage taps.
    {
        const float* w0 = w + (2 * cpi) * KK;
#pragma unroll
        for (int p = 0; p < NPAIR; p++)
            ws4[p][tid] = make_float4(__ldg(w0 + 2 * p),      __ldg(w0 + KK + 2 * p),
                                      __ldg(w0 + 2 * p + 1),  __ldg(w0 + KK + 2 * p + 1));
        ws30[tid] = make_float2(__ldg(w0 + 30), __ldg(w0 + KK + 30));
    }
    __syncthreads();

    const uint32_t ws4a  = (uint32_t)__cvta_generic_to_shared(&ws4[0][tid]);
    const uint32_t ws30a = (uint32_t)__cvta_generic_to_shared(&ws30[tid]);

    // Initial window: offsets 0..33. Predicate only bites when l0==0.
    float2 buf[WBUF];
#pragma unroll
    for (int i = 0; i < WBUF; i++) {
        const int l = base + i;
        buf[i] = (l >= 0) ? xb[(size_t)l * CPAIR] : make_float2(0.0f, 0.0f);
    }

#pragma unroll
    for (int c = 0; c < NCHUNK; c++) {
        float2 acc[CHUNK];
#pragma unroll
        for (int j = 0; j < CHUNK; j++) acc[j] = make_float2(0.0f, 0.0f);

        // 3-slot rotating tap-pair buffer (lead = 3 pairs > LDS latency)
        // + tap 30 loaded early.
        float4 wr[3];
        wr[0] = lds_w4(ws4a + 0 * (THREADS * 16));
        wr[1] = lds_w4(ws4a + 1 * (THREADS * 16));
        wr[2] = lds_w4(ws4a + 2 * (THREADS * 16));
        const float2 w30 = lds_w2(ws30a);

#pragma unroll
        for (int p = 0; p < NPAIR; p++) {
            const float4 q = wr[p % 3];
            const float2 wa = make_float2(q.x, q.y);     // tap 2p
            const float2 wb = make_float2(q.z, q.w);     // tap 2p+1
#pragma unroll
            for (int j = 0; j < CHUNK; j++)
                acc[j] = ffma2(wa, buf[(CHUNK * c + j + 2 * p) % WBUF], acc[j]);
#pragma unroll
            for (int j = 0; j < CHUNK; j++)
                acc[j] = ffma2(wb, buf[(CHUNK * c + j + 2 * p + 1) % WBUF], acc[j]);
            if (p + 3 < NPAIR)
                wr[p % 3] = lds_w4(ws4a + (uint32_t)(p + 3) * (THREADS * 16));
        }
        // Tap 30.
#pragma unroll
        for (int j = 0; j < CHUNK; j++)
            acc[j] = ffma2(w30, buf[(CHUNK * c + j + 30) % WBUF], acc[j]);

#pragma unroll
        for (int j = 0; j < CHUNK; j++)
            stg_cs(yb + (size_t)(CHUNK * c + j) * CPAIR, acc[j]);

        // Prefetch offsets 4c+34 .. 4c+37 into the slots chunk c retired.
        // l = l0 + 4 + 4c + i: always in [l0+4, l0+127] -> in range.
        if (c < NCHUNK - 1) {
#pragma unroll
            for (int i = 0; i < CHUNK; i++) {
                const int off = CHUNK * c + WBUF + i;
                buf[(CHUNK * c + i) % WBUF] = xb[(size_t)(base + off) * CPAIR];
            }
        }
    }
}

extern "C" void kernel_launch(void* const* d_in, const int* in_sizes, int n_in,
                              void* d_out, int out_size) {
    const float* x = (const float*)d_in[0];   // (8, 4096, 16, 128)
    const float* w = (const float*)d_in[1];   // (16, 128, 31)
    float* yv = (float*)d_out;

    dim3 grid(CPAIR / THREADS, LL / TT, BB);  // (16, 32, 8) = 4096 blocks
    _DepthwiseFIRConv1d_kernel<<<grid, THREADS>>>(x, w, yv);
}

// round 12
// speedup vs baseline: 1.2472x; 1.2472x over previous
#include <cuda_runtime.h>
#include <cstdint>

// Depthwise causal FIR conv1d, K=31, fp32.
// x: (8, 4096, 2048) channel-last.  w: (2048, 31).  y like x.
//
// Round-12: R8 design (38-slot register window + pinned smem taps) with
//  (a) __launch_bounds__(64, 7): 144-reg cap. R8's true demand is in
//      (128, 160] (uncapped pads to 160, cap 128 spills); 144 targets the
//      gap -> 7 blocks = 14 warps/SM, hopefully spill-free.
//  (b) prefetch LDGs interleaved into the tap loop: slot (8c+t)%38 retires
//      after tap group t, so its refill issues there with a (31-t)-tap lead.

#define BB 8
#define LL 4096
#define CPAIR 1024
#define KK 31
#define CHUNK 8
#define TT 128
#define NCHUNK 16
#define WBUF 38
#define THREADS 64

__device__ __forceinline__ float2 ffma2(float2 a, float2 b, float2 c) {
    float2 d;
    asm("fma.rn.f32x2 %0, %1, %2, %3;"
        : "=l"(*reinterpret_cast<unsigned long long*>(&d))
        : "l"(*reinterpret_cast<const unsigned long long*>(&a)),
          "l"(*reinterpret_cast<const unsigned long long*>(&b)),
          "l"(*reinterpret_cast<const unsigned long long*>(&c)));
    return d;
}

// Pinned LDS.64: volatile keeps ptxas from hoisting/batching weight loads
// (the hoist is what spilled R7).
__device__ __forceinline__ float2 lds_wt(uint32_t addr) {
    float2 v;
    asm volatile("ld.shared.v2.f32 {%0, %1}, [%2];"
                 : "=f"(v.x), "=f"(v.y) : "r"(addr));
    return v;
}

__global__ __launch_bounds__(THREADS, 7)
void _DepthwiseFIRConv1d_kernel(const float* __restrict__ x,
                                const float* __restrict__ w,
                                float* __restrict__ y) {
    __shared__ float2 ws[KK][THREADS];                   // 15872 B

    const int tid = threadIdx.x;
    const int cpi = blockIdx.x * THREADS + tid;          // channel pair 0..1023
    const int l0  = blockIdx.y * TT;
    const int b   = blockIdx.z;

    const float2* xb = reinterpret_cast<const float2*>(x) + (size_t)b * LL * CPAIR + cpi;
    float2*       yb = reinterpret_cast<float2*>(y) + ((size_t)b * LL + l0) * CPAIR + cpi;
    const int base = l0 - (KK - 1);

    // Stage taps into smem: ws[t][tid] = (w[2cp][t], w[2cp+1][t]).
    {
        const float* w0 = w + (2 * cpi) * KK;
#pragma unroll
        for (int t = 0; t < KK; t++)
            ws[t][tid] = make_float2(__ldg(w0 + t), __ldg(w0 + KK + t));
    }
    __syncthreads();

    const uint32_t ws0 = (uint32_t)__cvta_generic_to_shared(&ws[0][tid]);

    // Initial window: offsets 0..37. Predicate only bites when l0==0.
    float2 buf[WBUF];
#pragma unroll
    for (int i = 0; i < WBUF; i++) {
        const int l = base + i;
        buf[i] = (l >= 0) ? xb[(size_t)l * CPAIR] : make_float2(0.0f, 0.0f);
    }

#pragma unroll
    for (int c = 0; c < NCHUNK; c++) {
        float2 acc[CHUNK];
#pragma unroll
        for (int j = 0; j < CHUNK; j++) acc[j] = make_float2(0.0f, 0.0f);

        // 3-slot rotating weight buffer (3-tap lead >= LDS latency).
        float2 wr[3];
        wr[0] = lds_wt(ws0 + 0 * (THREADS * 8));
        wr[1] = lds_wt(ws0 + 1 * (THREADS * 8));
        wr[2] = lds_wt(ws0 + 2 * (THREADS * 8));

#pragma unroll
        for (int t = 0; t < KK; t++) {
            const float2 wt = wr[t % 3];
#pragma unroll
            for (int j = 0; j < CHUNK; j++)
                acc[j] = ffma2(wt, buf[(CHUNK * c + j + t) % WBUF], acc[j]);
            if (t + 3 < KK)
                wr[t % 3] = lds_wt(ws0 + (uint32_t)(t + 3) * (THREADS * 8));

            // Early prefetch: slot (8c+t)%38 was last read by this tap group.
            // Refill it with offset 8c+38+t (l = l0+8c+8+t, always in range).
            if (t < CHUNK && c < NCHUNK - 1) {
                const int off = CHUNK * c + WBUF + t;
                buf[(CHUNK * c + t) % WBUF] = xb[(size_t)(base + off) * CPAIR];
            }
        }

#pragma unroll
        for (int j = 0; j < CHUNK; j++)
            yb[(size_t)(CHUNK * c + j) * CPAIR] = acc[j];
    }
}

extern "C" void kernel_launch(void* const* d_in, const int* in_sizes, int n_in,
                              void* d_out, int out_size) {
    const float* x = (const float*)d_in[0];   // (8, 4096, 16, 128)
    const float* w = (const float*)d_in[1];   // (16, 128, 31)
    float* yv = (float*)d_out;

    dim3 grid(CPAIR / THREADS, LL / TT, BB);  // (16, 32, 8) = 4096 blocks
    _DepthwiseFIRConv1d_kernel<<<grid, THREADS>>>(x, w, yv);
}

// round 14
// speedup vs baseline: 2.8710x; 2.3019x over previous
#include <cuda_runtime.h>
#include <cstdint>

// Depthwise causal FIR conv1d, K=31, fp32.
// x: (8, 4096, 2048) channel-last.  w: (2048, 31).  y like x.
//
// Round-14: minimum-liveness register window (R13 + last-chunk refill fix).
//  - thread = channel pair (float2), TT=128 outputs, CHUNK=8, full unroll
//  - 30-slot circular window (exact live span): slot for offset 8c+t takes its
//    last read at tap t (j=0) and is refilled there with offset 8c+30+t; the
//    refilled value is first consumed at tap t+23 of the SAME chunk, so the
//    refill runs in EVERY chunk (R13 skipped chunk 15 -> stale data).
//  - taps: pinned smem (asm-volatile LDS.64, 3-slot rotation) -> no hoist
//  - NO launch_bounds cap (caps spilled in R7/R9/R11/R12); true demand ~115

#define BB 8
#define LL 4096
#define CPAIR 1024
#define KK 31
#define CHUNK 8
#define TT 128
#define NCHUNK 16
#define WBUF 30
#define THREADS 64

__device__ __forceinline__ float2 ffma2(float2 a, float2 b, float2 c) {
    float2 d;
    asm("fma.rn.f32x2 %0, %1, %2, %3;"
        : "=l"(*reinterpret_cast<unsigned long long*>(&d))
        : "l"(*reinterpret_cast<const unsigned long long*>(&a)),
          "l"(*reinterpret_cast<const unsigned long long*>(&b)),
          "l"(*reinterpret_cast<const unsigned long long*>(&c)));
    return d;
}

// Pinned LDS.64: volatile keeps ptxas from hoisting/batching weight loads.
__device__ __forceinline__ float2 lds_wt(uint32_t addr) {
    float2 v;
    asm volatile("ld.shared.v2.f32 {%0, %1}, [%2];"
                 : "=f"(v.x), "=f"(v.y) : "r"(addr));
    return v;
}

__global__ __launch_bounds__(THREADS)
void _DepthwiseFIRConv1d_kernel(const float* __restrict__ x,
                                const float* __restrict__ w,
                                float* __restrict__ y) {
    __shared__ float2 ws[KK][THREADS];                   // 15872 B

    const int tid = threadIdx.x;
    const int cpi = blockIdx.x * THREADS + tid;          // channel pair 0..1023
    const int l0  = blockIdx.y * TT;
    const int b   = blockIdx.z;

    const float2* xb = reinterpret_cast<const float2*>(x) + (size_t)b * LL * CPAIR + cpi;
    float2*       yb = reinterpret_cast<float2*>(y) + ((size_t)b * LL + l0) * CPAIR + cpi;
    const int base = l0 - (KK - 1);                      // x offset of window origin

    // Stage taps into smem: ws[t][tid] = (w[2cp][t], w[2cp+1][t]).
    {
        const float* w0 = w + (2 * cpi) * KK;
#pragma unroll
        for (int t = 0; t < KK; t++)
            ws[t][tid] = make_float2(__ldg(w0 + t), __ldg(w0 + KK + t));
    }
    __syncthreads();

    const uint32_t ws0 = (uint32_t)__cvta_generic_to_shared(&ws[0][tid]);

    // Initial window: offsets 0..29 (l = l0-30 .. l0-1). Predicated for l0==0.
    float2 buf[WBUF];
#pragma unroll
    for (int i = 0; i < WBUF; i++) {
        const int l = base + i;
        buf[i] = (l >= 0) ? xb[(size_t)l * CPAIR] : make_float2(0.0f, 0.0f);
    }

#pragma unroll
    for (int c = 0; c < NCHUNK; c++) {
        float2 acc[CHUNK];
#pragma unroll
        for (int j = 0; j < CHUNK; j++) acc[j] = make_float2(0.0f, 0.0f);

        // 3-slot rotating weight buffer (3-tap lead >= LDS latency).
        float2 wr[3];
        wr[0] = lds_wt(ws0 + 0 * (THREADS * 8));
        wr[1] = lds_wt(ws0 + 1 * (THREADS * 8));
        wr[2] = lds_wt(ws0 + 2 * (THREADS * 8));

#pragma unroll
        for (int t = 0; t < KK; t++) {
            const float2 wt = wr[t % 3];
#pragma unroll
            for (int j = 0; j < CHUNK; j++)
                acc[j] = ffma2(wt, buf[(CHUNK * c + t + j) % WBUF], acc[j]);

            if (t + 3 < KK)
                wr[t % 3] = lds_wt(ws0 + (uint32_t)(t + 3) * (THREADS * 8));

            // Slot (8c+t)%30 just took its last read (j=0 above). Refill with
            // offset 8c+30+t; first consumer is tap t+23 of THIS chunk, so
            // this must run for every chunk including the last.
            // l = base + 8c + 30 + t = l0 + 8c + t: always in [l0, l0+127].
            if (t < CHUNK) {
                const int off = CHUNK * c + WBUF + t;
                buf[(CHUNK * c + t) % WBUF] = xb[(size_t)(base + off) * CPAIR];
            }
        }

#pragma unroll
        for (int j = 0; j < CHUNK; j++)
            yb[(size_t)(CHUNK * c + j) * CPAIR] = acc[j];
    }
}

extern "C" void kernel_launch(void* const* d_in, const int* in_sizes, int n_in,
                              void* d_out, int out_size) {
    const float* x = (const float*)d_in[0];   // (8, 4096, 16, 128)
    const float* w = (const float*)d_in[1];   // (16, 128, 31)
    float* yv = (float*)d_out;

    dim3 grid(CPAIR / THREADS, LL / TT, BB);  // (16, 32, 8) = 4096 blocks
    _DepthwiseFIRConv1d_kernel<<<grid, THREADS>>>(x, w, yv);
}